// round 10
// baseline (speedup 1.0000x reference)
#include <cuda_runtime.h>
#include <cstdint>

// DepthwiseStencil3D, persistent output-linear variant (R9 + long streams).
// out flat channel ch = c*6+k is x[c] shifted by tap k, zero-padded.
// Taps: 0 -> w+1, 1 -> w-1, 2 -> h+1, 3 -> h-1, 4 -> d+1, 5 -> d-1.
//
// 444 persistent CTAs (148 SMs x 3). Each CTA sweeps 56 consecutive 8192-elem
// regions of the output (1.8 MB strictly sequential writes per CTA). Per
// region: 4 chunks/thread, 256-bit evict_last loads, 256-bit evict-first
// streaming stores, warp-shuffle w-taps.

#define C_ 16
#define D_ 128
#define H_ 128
#define W_ 128
#define HW_ (H_ * W_)          // 16384
#define DHW_ (D_ * HW_)        // 2097152
#define NREGIONS 24576         // 96 channels * 256 regions
#define REG_PER_CTA 56

struct V8 { uint32_t r[8]; };

__device__ __forceinline__ V8 ldg_v8_el(const float* p) {
    V8 v;
    asm volatile(
        "{ .reg .b64 pol;\n"
        "  createpolicy.fractional.L2::evict_last.b64 pol, 1.0;\n"
        "  ld.global.L2::cache_hint.v8.b32 {%0,%1,%2,%3,%4,%5,%6,%7}, [%8], pol; }\n"
        : "=r"(v.r[0]), "=r"(v.r[1]), "=r"(v.r[2]), "=r"(v.r[3]),
          "=r"(v.r[4]), "=r"(v.r[5]), "=r"(v.r[6]), "=r"(v.r[7])
        : "l"(p));
    return v;
}

__device__ __forceinline__ void stg_cs_v8(float* p, const V8& v) {
    asm volatile("st.global.cs.v8.b32 [%0], {%1,%2,%3,%4,%5,%6,%7,%8};"
                 :: "l"(p),
                    "r"(v.r[0]), "r"(v.r[1]), "r"(v.r[2]), "r"(v.r[3]),
                    "r"(v.r[4]), "r"(v.r[5]), "r"(v.r[6]), "r"(v.r[7])
                 : "memory");
}

__global__ void __launch_bounds__(256) stencil6_kernel(
    const float* __restrict__ x, float* __restrict__ out)
{
    int t = threadIdx.x;
    int region0 = blockIdx.x * REG_PER_CTA;

    V8 zero;
#pragma unroll
    for (int i = 0; i < 8; i++) zero.r[i] = 0u;

    for (int r = 0; r < REG_PER_CTA; r++) {
        int region = region0 + r;
        if (region >= NREGIONS) break;

        int ch  = region >> 8;        // output channel 0..95
        int reg = region & 255;       // 8192-elem region within channel
        int c   = ch / 6;
        int k   = ch - 6 * c;         // tap kind (uniform per warp)

        const float* __restrict__ xc = x + c * DHW_;
        float* __restrict__ ob = out + ch * DHW_;

        int off0 = (reg << 13) + (t << 3);

        V8 res[4];

        if (k < 2) {
            unsigned full = 0xffffffffu;
            int w8 = t & 15;          // 8-float chunk index within the W row
            V8 v[4];
#pragma unroll
            for (int i = 0; i < 4; i++) v[i] = ldg_v8_el(xc + off0 + (i << 11));

            if (k == 0) {             // w+1
#pragma unroll
                for (int i = 0; i < 4; i++) {
                    uint32_t xr = __shfl_down_sync(full, v[i].r[0], 1);
                    if (w8 == 15) xr = 0u;
#pragma unroll
                    for (int j = 0; j < 7; j++) res[i].r[j] = v[i].r[j + 1];
                    res[i].r[7] = xr;
                }
            } else {                  // w-1
#pragma unroll
                for (int i = 0; i < 4; i++) {
                    uint32_t xl = __shfl_up_sync(full, v[i].r[7], 1);
                    if (w8 == 0) xl = 0u;
                    res[i].r[0] = xl;
#pragma unroll
                    for (int j = 1; j < 8; j++) res[i].r[j] = v[i].r[j - 1];
                }
            }
        } else {
            int delta = (k == 2) ?  W_  :
                        (k == 3) ? -W_  :
                        (k == 4) ?  HW_ : -HW_;
#pragma unroll
            for (int i = 0; i < 4; i++) {
                int o = off0 + (i << 11);
                bool ok;
                if      (k == 2) ok = ((o >> 7) & 127) < H_ - 1;  // h < 127
                else if (k == 3) ok = ((o >> 7) & 127) > 0;       // h > 0
                else if (k == 4) ok = (o >> 14) < D_ - 1;         // d < 127
                else             ok = (o >> 14) > 0;              // d > 0
                res[i] = ok ? ldg_v8_el(xc + o + delta) : zero;
            }
        }

#pragma unroll
        for (int i = 0; i < 4; i++) stg_cs_v8(ob + off0 + (i << 11), res[i]);
    }
}

extern "C" void kernel_launch(void* const* d_in, const int* in_sizes, int n_in,
                              void* d_out, int out_size)
{
    const float* x = (const float*)d_in[0];
    float* out = (float*)d_out;

    // 444 persistent CTAs (148 SMs x 3), each sweeps 56 regions (1.8 MB).
    stencil6_kernel<<<444, 256>>>(x, out);
}

// round 11
// speedup vs baseline: 1.6539x; 1.6539x over previous
#include <cuda_runtime.h>
#include <cstdint>

// DepthwiseStencil3D, output-linear variant v4 (R9 + fused w-taps).
// out flat channel ch = c*6+k is x[c] shifted by tap k, zero-padded.
// Taps: 0 -> w+1, 1 -> w-1, 2 -> h+1, 3 -> h-1, 4 -> d+1, 5 -> d-1.
//
// Two CTA kinds, all 256 threads, all writing 32 KB-contiguous-per-channel:
//  - pair CTAs (k=0,1): ONE 256-bit load per chunk produces BOTH w-shift
//    outputs (register shuffle), stored to channels 6c and 6c+1.
//  - copy CTAs (k=2..5): pure shifted copy, 1 load + 1 store per chunk.
// Loads are L2 evict_last (input stays resident); stores evict-first.

#define C_ 16
#define D_ 128
#define H_ 128
#define W_ 128
#define HW_ (H_ * W_)          // 16384
#define DHW_ (D_ * HW_)        // 2097152

#define PAIR_BLOCKS (C_ * 256)         // 4096: (c, region)
#define COPY_BLOCKS (C_ * 4 * 256)     // 16384: (c, k-2, region)

struct V8 { uint32_t r[8]; };

__device__ __forceinline__ V8 ldg_v8_el(const float* p) {
    V8 v;
    asm volatile(
        "{ .reg .b64 pol;\n"
        "  createpolicy.fractional.L2::evict_last.b64 pol, 1.0;\n"
        "  ld.global.L2::cache_hint.v8.b32 {%0,%1,%2,%3,%4,%5,%6,%7}, [%8], pol; }\n"
        : "=r"(v.r[0]), "=r"(v.r[1]), "=r"(v.r[2]), "=r"(v.r[3]),
          "=r"(v.r[4]), "=r"(v.r[5]), "=r"(v.r[6]), "=r"(v.r[7])
        : "l"(p));
    return v;
}

__device__ __forceinline__ void stg_cs_v8(float* p, const V8& v) {
    asm volatile("st.global.cs.v8.b32 [%0], {%1,%2,%3,%4,%5,%6,%7,%8};"
                 :: "l"(p),
                    "r"(v.r[0]), "r"(v.r[1]), "r"(v.r[2]), "r"(v.r[3]),
                    "r"(v.r[4]), "r"(v.r[5]), "r"(v.r[6]), "r"(v.r[7])
                 : "memory");
}

__global__ void __launch_bounds__(256) stencil6_kernel(
    const float* __restrict__ x, float* __restrict__ out)
{
    int t   = threadIdx.x;
    int bid = blockIdx.x;

    V8 zero;
#pragma unroll
    for (int i = 0; i < 8; i++) zero.r[i] = 0u;

    if (bid < PAIR_BLOCKS) {
        // ---- fused w-taps: channels 6c (w+1) and 6c+1 (w-1) ----
        int c   = bid >> 8;
        int reg = bid & 255;
        const float* __restrict__ xc = x + c * DHW_;
        float* __restrict__ ob0 = out + (c * 6) * DHW_;      // k=0
        float* __restrict__ ob1 = ob0 + DHW_;                // k=1

        int off0 = (reg << 13) + (t << 3);
        unsigned full = 0xffffffffu;
        int w8 = t & 15;              // 8-float chunk index within the W row

#pragma unroll
        for (int i = 0; i < 4; i++) {
            int o = off0 + (i << 11);
            V8 v = ldg_v8_el(xc + o);

            uint32_t xr = __shfl_down_sync(full, v.r[0], 1);
            uint32_t xl = __shfl_up_sync(full, v.r[7], 1);
            if (w8 == 15) xr = 0u;
            if (w8 == 0)  xl = 0u;

            V8 k0, k1;
#pragma unroll
            for (int j = 0; j < 7; j++) k0.r[j] = v.r[j + 1];
            k0.r[7] = xr;
            k1.r[0] = xl;
#pragma unroll
            for (int j = 1; j < 8; j++) k1.r[j] = v.r[j - 1];

            stg_cs_v8(ob0 + o, k0);
            stg_cs_v8(ob1 + o, k1);
        }
    } else {
        // ---- copy taps k = 2..5: pure shifted copy with zero padding ----
        int b   = bid - PAIR_BLOCKS;
        int reg = b & 255;
        int k   = ((b >> 8) & 3) + 2;
        int c   = b >> 10;

        const float* __restrict__ xc = x + c * DHW_;
        float* __restrict__ ob = out + (c * 6 + k) * DHW_;

        int off0 = (reg << 13) + (t << 3);
        int delta = (k == 2) ?  W_  :
                    (k == 3) ? -W_  :
                    (k == 4) ?  HW_ : -HW_;

        V8 res[4];
#pragma unroll
        for (int i = 0; i < 4; i++) {
            int o = off0 + (i << 11);
            bool ok;
            if      (k == 2) ok = ((o >> 7) & 127) < H_ - 1;  // h < 127
            else if (k == 3) ok = ((o >> 7) & 127) > 0;       // h > 0
            else if (k == 4) ok = (o >> 14) < D_ - 1;         // d < 127
            else             ok = (o >> 14) > 0;              // d > 0
            res[i] = ok ? ldg_v8_el(xc + o + delta) : zero;
        }
#pragma unroll
        for (int i = 0; i < 4; i++) stg_cs_v8(ob + off0 + (i << 11), res[i]);
    }
}

extern "C" void kernel_launch(void* const* d_in, const int* in_sizes, int n_in,
                              void* d_out, int out_size)
{
    const float* x = (const float*)d_in[0];
    float* out = (float*)d_out;

    // 4096 pair CTAs + 16384 copy CTAs; every CTA writes 32 KB-contiguous
    // streams in channel-linear order.
    stencil6_kernel<<<PAIR_BLOCKS + COPY_BLOCKS, 256>>>(x, out);
}

// round 12
// speedup vs baseline: 1.9075x; 1.1533x over previous
#include <cuda_runtime.h>
#include <cstdint>

// DepthwiseStencil3D, output-linear variant v5 (R9 body + reader-co-scheduled grid).
// out flat channel ch = c*6+k is x[c] shifted by tap k, zero-padded.
// Taps: 0 -> w+1, 1 -> w-1, 2 -> h+1, 3 -> h-1, 4 -> d+1, 5 -> d-1.
//
// Each 256-thread CTA owns one contiguous 8192-element (32 KB) region of ONE
// output channel. Grid order: bid = (c*256 + reg)*6 + k, so the six taps
// reading the same input region are adjacent bids (co-resident -> 1 DRAM read
// + 5 L2 hits) while same-channel writers stay on consecutive regions.
// Loads are L2 evict_last; stores evict-first streaming 256-bit.

#define C_ 16
#define D_ 128
#define H_ 128
#define W_ 128
#define HW_ (H_ * W_)          // 16384
#define DHW_ (D_ * HW_)        // 2097152

struct V8 { uint32_t r[8]; };

__device__ __forceinline__ V8 ldg_v8_el(const float* p) {
    V8 v;
    asm volatile(
        "{ .reg .b64 pol;\n"
        "  createpolicy.fractional.L2::evict_last.b64 pol, 1.0;\n"
        "  ld.global.L2::cache_hint.v8.b32 {%0,%1,%2,%3,%4,%5,%6,%7}, [%8], pol; }\n"
        : "=r"(v.r[0]), "=r"(v.r[1]), "=r"(v.r[2]), "=r"(v.r[3]),
          "=r"(v.r[4]), "=r"(v.r[5]), "=r"(v.r[6]), "=r"(v.r[7])
        : "l"(p));
    return v;
}

__device__ __forceinline__ void stg_cs_v8(float* p, const V8& v) {
    asm volatile("st.global.cs.v8.b32 [%0], {%1,%2,%3,%4,%5,%6,%7,%8};"
                 :: "l"(p),
                    "r"(v.r[0]), "r"(v.r[1]), "r"(v.r[2]), "r"(v.r[3]),
                    "r"(v.r[4]), "r"(v.r[5]), "r"(v.r[6]), "r"(v.r[7])
                 : "memory");
}

__global__ void __launch_bounds__(256) stencil6_kernel(
    const float* __restrict__ x, float* __restrict__ out)
{
    int t   = threadIdx.x;
    int bid = blockIdx.x;

    // bid = (c*256 + reg)*6 + k
    int k  = bid % 6;
    int cr = bid / 6;             // c*256 + reg
    int reg = cr & 255;
    int c   = cr >> 8;
    int ch  = c * 6 + k;

    const float* __restrict__ xc = x + c * DHW_;
    float* __restrict__ ob = out + ch * DHW_;

    int off0 = (reg << 13) + (t << 3);

    V8 zero;
#pragma unroll
    for (int i = 0; i < 8; i++) zero.r[i] = 0u;

    V8 res[4];

    if (k < 2) {
        // w-shift taps: aligned load + lane shuffle for the edge scalar.
        unsigned full = 0xffffffffu;
        int w8 = t & 15;          // 8-float chunk index within the W row
        V8 v[4];
#pragma unroll
        for (int i = 0; i < 4; i++) v[i] = ldg_v8_el(xc + off0 + (i << 11));

        if (k == 0) {             // w+1
#pragma unroll
            for (int i = 0; i < 4; i++) {
                uint32_t xr = __shfl_down_sync(full, v[i].r[0], 1);
                if (w8 == 15) xr = 0u;
#pragma unroll
                for (int j = 0; j < 7; j++) res[i].r[j] = v[i].r[j + 1];
                res[i].r[7] = xr;
            }
        } else {                  // w-1
#pragma unroll
            for (int i = 0; i < 4; i++) {
                uint32_t xl = __shfl_up_sync(full, v[i].r[7], 1);
                if (w8 == 0) xl = 0u;
                res[i].r[0] = xl;
#pragma unroll
                for (int j = 1; j < 8; j++) res[i].r[j] = v[i].r[j - 1];
            }
        }
    } else {
        // h/d-shift taps: pure shifted copies with zero padding at the edge.
        int delta = (k == 2) ?  W_  :
                    (k == 3) ? -W_  :
                    (k == 4) ?  HW_ : -HW_;
#pragma unroll
        for (int i = 0; i < 4; i++) {
            int o = off0 + (i << 11);
            bool ok;
            if      (k == 2) ok = ((o >> 7) & 127) < H_ - 1;  // h < 127
            else if (k == 3) ok = ((o >> 7) & 127) > 0;       // h > 0
            else if (k == 4) ok = (o >> 14) < D_ - 1;         // d < 127
            else             ok = (o >> 14) > 0;              // d > 0
            res[i] = ok ? ldg_v8_el(xc + o + delta) : zero;
        }
    }

#pragma unroll
    for (int i = 0; i < 4; i++) stg_cs_v8(ob + off0 + (i << 11), res[i]);
}

extern "C" void kernel_launch(void* const* d_in, const int* in_sizes, int n_in,
                              void* d_out, int out_size)
{
    const float* x = (const float*)d_in[0];
    float* out = (float*)d_out;

    // 16 c * 256 regions * 6 taps = 24576 CTAs; each writes 32 KB contiguous.
    stencil6_kernel<<<24576, 256>>>(x, out);
}

// round 13
// speedup vs baseline: 1.9625x; 1.0288x over previous
#include <cuda_runtime.h>
#include <cstdint>

// DepthwiseStencil3D, output-linear variant v6 (R9 with 16 KB regions).
// out flat channel ch = c*6+k is x[c] shifted by tap k, zero-padded.
// Taps: 0 -> w+1, 1 -> w-1, 2 -> h+1, 3 -> h-1, 4 -> d+1, 5 -> d-1.
//
// Each 256-thread CTA owns one contiguous 4096-element (16 KB) region of ONE
// output channel; channel-major grid keeps consecutive bids on consecutive
// regions (linear write sweep). 2 chunks/thread, 256-bit evict_last loads,
// 256-bit evict-first streaming stores, warp-shuffle w-taps.

#define C_ 16
#define D_ 128
#define H_ 128
#define W_ 128
#define HW_ (H_ * W_)          // 16384
#define DHW_ (D_ * HW_)        // 2097152

struct V8 { uint32_t r[8]; };

__device__ __forceinline__ V8 ldg_v8_el(const float* p) {
    V8 v;
    asm volatile(
        "{ .reg .b64 pol;\n"
        "  createpolicy.fractional.L2::evict_last.b64 pol, 1.0;\n"
        "  ld.global.L2::cache_hint.v8.b32 {%0,%1,%2,%3,%4,%5,%6,%7}, [%8], pol; }\n"
        : "=r"(v.r[0]), "=r"(v.r[1]), "=r"(v.r[2]), "=r"(v.r[3]),
          "=r"(v.r[4]), "=r"(v.r[5]), "=r"(v.r[6]), "=r"(v.r[7])
        : "l"(p));
    return v;
}

__device__ __forceinline__ void stg_cs_v8(float* p, const V8& v) {
    asm volatile("st.global.cs.v8.b32 [%0], {%1,%2,%3,%4,%5,%6,%7,%8};"
                 :: "l"(p),
                    "r"(v.r[0]), "r"(v.r[1]), "r"(v.r[2]), "r"(v.r[3]),
                    "r"(v.r[4]), "r"(v.r[5]), "r"(v.r[6]), "r"(v.r[7])
                 : "memory");
}

__global__ void __launch_bounds__(256) stencil6_kernel(
    const float* __restrict__ x, float* __restrict__ out)
{
    int t   = threadIdx.x;
    int bid = blockIdx.x;

    int ch  = bid >> 9;           // output channel 0..95
    int reg = bid & 511;          // 4096-element region within channel
    int c   = ch / 6;
    int k   = ch - 6 * c;         // tap kind, uniform per CTA

    const float* __restrict__ xc = x + c * DHW_;
    float* __restrict__ ob = out + ch * DHW_;

    int off0 = (reg << 12) + (t << 3);

    V8 zero;
#pragma unroll
    for (int i = 0; i < 8; i++) zero.r[i] = 0u;

    V8 res[2];

    if (k < 2) {
        // w-shift taps: aligned load + lane shuffle for the edge scalar.
        unsigned full = 0xffffffffu;
        int w8 = t & 15;          // 8-float chunk index within the W row
        V8 v[2];
#pragma unroll
        for (int i = 0; i < 2; i++) v[i] = ldg_v8_el(xc + off0 + (i << 11));

        if (k == 0) {             // w+1
#pragma unroll
            for (int i = 0; i < 2; i++) {
                uint32_t xr = __shfl_down_sync(full, v[i].r[0], 1);
                if (w8 == 15) xr = 0u;
#pragma unroll
                for (int j = 0; j < 7; j++) res[i].r[j] = v[i].r[j + 1];
                res[i].r[7] = xr;
            }
        } else {                  // w-1
#pragma unroll
            for (int i = 0; i < 2; i++) {
                uint32_t xl = __shfl_up_sync(full, v[i].r[7], 1);
                if (w8 == 0) xl = 0u;
                res[i].r[0] = xl;
#pragma unroll
                for (int j = 1; j < 8; j++) res[i].r[j] = v[i].r[j - 1];
            }
        }
    } else {
        // h/d-shift taps: pure shifted copies with zero padding at the edge.
        int delta = (k == 2) ?  W_  :
                    (k == 3) ? -W_  :
                    (k == 4) ?  HW_ : -HW_;
#pragma unroll
        for (int i = 0; i < 2; i++) {
            int o = off0 + (i << 11);
            bool ok;
            if      (k == 2) ok = ((o >> 7) & 127) < H_ - 1;  // h < 127
            else if (k == 3) ok = ((o >> 7) & 127) > 0;       // h > 0
            else if (k == 4) ok = (o >> 14) < D_ - 1;         // d < 127
            else             ok = (o >> 14) > 0;              // d > 0
            res[i] = ok ? ldg_v8_el(xc + o + delta) : zero;
        }
    }

#pragma unroll
    for (int i = 0; i < 2; i++) stg_cs_v8(ob + off0 + (i << 11), res[i]);
}

extern "C" void kernel_launch(void* const* d_in, const int* in_sizes, int n_in,
                              void* d_out, int out_size)
{
    const float* x = (const float*)d_in[0];
    float* out = (float*)d_out;

    // 96 channels * 512 regions = 49152 CTAs; each writes 16 KB contiguous.
    stencil6_kernel<<<49152, 256>>>(x, out);
}